// round 15
// baseline (speedup 1.0000x reference)
#include <cuda_runtime.h>
#include <cuda_fp16.h>

// Problem constants (from reference): N=50000, D=128, E=625000
#define N_NODE   50000
#define D_FEAT   128
#define N_EDGE_MAX 625000
#define SIM_THRESH 0.1f
#define BAND 2.0e-3f   // rigorous fp16 dot error bound is ~1.1e-3; 2e-3 is safe

// Scratch (device globals — no allocation allowed in kernel_launch)
__device__ float g_inv_nrm[N_NODE];           // 1 / max(||f||, 1e-12)
__device__ float g_row_sum[N_NODE];           // L1 row sums of thresholded sim
__device__ __align__(16) float g_sim[N_EDGE_MAX];  // thresholded per-edge sim (exact fp32)
__device__ __align__(16) __half g_fn[(size_t)N_NODE * D_FEAT];  // normalized fp16 feats

// ---------------------------------------------------------------------------
// Kernel 1: per-node inverse norm — 2 nodes per warp (measured best: 9.28us,
// occ 85%), writes normalized fp16 features, zeroes row_sum. PDL trigger
// before the store phase.
// ---------------------------------------------------------------------------
__global__ void norm_kernel(const float* __restrict__ feat, int n_node) {
    int tid  = blockIdx.x * blockDim.x + threadIdx.x;
    int warp = tid >> 5;
    int lane = threadIdx.x & 31;

    if (tid < n_node) g_row_sum[tid] = 0.0f;

    int n0 = warp * 2;
    int n1 = warp * 2 + 1;
    if (n0 >= n_node) return;
    bool has1 = (n1 < n_node);

    const float4* F = reinterpret_cast<const float4*>(feat);
    float4 a0 = F[(size_t)n0 * 32 + lane];
    float4 a1 = has1 ? F[(size_t)n1 * 32 + lane] : make_float4(0, 0, 0, 0);

    float s0 = a0.x * a0.x + a0.y * a0.y + a0.z * a0.z + a0.w * a0.w;
    float s1 = a1.x * a1.x + a1.y * a1.y + a1.z * a1.z + a1.w * a1.w;
    #pragma unroll
    for (int off = 16; off > 0; off >>= 1) {
        s0 += __shfl_xor_sync(0xFFFFFFFFu, s0, off);
        s1 += __shfl_xor_sync(0xFFFFFFFFu, s1, off);
    }

    cudaTriggerProgrammaticLaunchCompletion();

    float inv0 = 1.0f / fmaxf(sqrtf(s0), 1e-12f);
    float inv1 = 1.0f / fmaxf(sqrtf(s1), 1e-12f);
    if (lane == 0) {
        g_inv_nrm[n0] = inv0;
        if (has1) g_inv_nrm[n1] = inv1;
    }

    {
        __half2 h0 = __floats2half2_rn(a0.x * inv0, a0.y * inv0);
        __half2 h1 = __floats2half2_rn(a0.z * inv0, a0.w * inv0);
        uint2 p;
        p.x = *reinterpret_cast<unsigned*>(&h0);
        p.y = *reinterpret_cast<unsigned*>(&h1);
        reinterpret_cast<uint2*>(g_fn + (size_t)n0 * D_FEAT)[lane] = p;
    }
    if (has1) {
        __half2 h0 = __floats2half2_rn(a1.x * inv1, a1.y * inv1);
        __half2 h1 = __floats2half2_rn(a1.z * inv1, a1.w * inv1);
        uint2 p;
        p.x = *reinterpret_cast<unsigned*>(&h0);
        p.y = *reinterpret_cast<unsigned*>(&h1);
        reinterpret_cast<uint2*>(g_fn + (size_t)n1 * D_FEAT)[lane] = p;
    }
}

// ---------------------------------------------------------------------------
// Kernel 2: 8 edges per warp — 16 lanes per edge, LDG.128 fp16 gathers
// (8 front-batched loads = MLP 8), coalesced+shuffled index loads,
// pair-batched exact fp32 recompute for edges whose fp16 sim could pass the
// threshold (~14%). PDL trigger AFTER the recompute (measured: early trigger
// lets finish's grid interfere with the recompute phase, net loss).
// ---------------------------------------------------------------------------
__global__ void sim_kernel(const int* __restrict__ ei,
                           const float* __restrict__ feat,
                           int n_edge) {
    int warp = (blockIdx.x * blockDim.x + threadIdx.x) >> 5;
    int lane = threadIdx.x & 31;
    int half = lane >> 4;          // 0 or 1
    int hl   = lane & 15;          // lane within half-warp
    unsigned hmask = half ? 0xFFFF0000u : 0x0000FFFFu;

    long long e_base = (long long)warp * 8;
    if (e_base >= n_edge) { cudaGridDependencySynchronize(); return; }

    // ---- PDL prologue: edge indices are harness inputs, independent of norm
    int v = 0;
    {
        long long e = e_base + (lane & 7);
        if (lane < 16 && e < n_edge) {
            long long pos = (lane & 8) ? (long long)n_edge + e : e;
            v = ei[pos];
        }
    }
    int r[4], c[4];
    bool valid[4];
    #pragma unroll
    for (int k = 0; k < 4; k++) {
        int src = 2 * k + half;                       // this half-warp's edge
        r[k] = __shfl_sync(0xFFFFFFFFu, v, src);
        c[k] = __shfl_sync(0xFFFFFFFFu, v, 8 + src);
        valid[k] = (e_base + src) < n_edge;
    }

    // ---- wait for norm_kernel's writes (g_fn, g_inv_nrm, g_row_sum)
    cudaGridDependencySynchronize();

    // batched fp16 gathers: 8 independent LDG.128 (16 lanes x 16B = 256B/row)
    uint4 pa[4], pb[4];
    #pragma unroll
    for (int k = 0; k < 4; k++) {
        pa[k] = reinterpret_cast<const uint4*>(g_fn + (size_t)r[k] * D_FEAT)[hl];
        pb[k] = reinterpret_cast<const uint4*>(g_fn + (size_t)c[k] * D_FEAT)[hl];
    }

    float acc[4];
    #pragma unroll
    for (int k = 0; k < 4; k++) {
        const __half2* ha = reinterpret_cast<const __half2*>(&pa[k]);
        const __half2* hb = reinterpret_cast<const __half2*>(&pb[k]);
        float d = 0.0f;
        #pragma unroll
        for (int j = 0; j < 4; j++) {
            float2 x = __half22float2(ha[j]);
            float2 y = __half22float2(hb[j]);
            d += x.x * y.x + x.y * y.y;
        }
        acc[k] = d;
    }
    // interleaved 4-level half-warp reductions
    #pragma unroll
    for (int off = 8; off > 0; off >>= 1) {
        #pragma unroll
        for (int k = 0; k < 4; k++)
            acc[k] += __shfl_xor_sync(hmask, acc[k], off);
    }

    bool need[4];
    #pragma unroll
    for (int k = 0; k < 4; k++)
        need[k] = valid[k] && (acc[k] >= SIM_THRESH - BAND);  // half-warp uniform

    float s[4] = {0.0f, 0.0f, 0.0f, 0.0f};
    const float4* F = reinterpret_cast<const float4*>(feat);
    #pragma unroll
    for (int kk = 0; kk < 4; kk += 2) {
        float4 A0[2], A1[2], B0[2], B1[2];
        #pragma unroll
        for (int j = 0; j < 2; j++) {
            int k = kk + j;
            if (need[k]) {   // batch both edges' loads before either reduction
                const float4* FR = F + (size_t)r[k] * 32;
                const float4* FC = F + (size_t)c[k] * 32;
                A0[j] = FR[hl];      B0[j] = FC[hl];
                A1[j] = FR[hl + 16]; B1[j] = FC[hl + 16];
            }
        }
        #pragma unroll
        for (int j = 0; j < 2; j++) {
            int k = kk + j;
            if (need[k]) {
                float d = A0[j].x * B0[j].x + A0[j].y * B0[j].y
                        + A0[j].z * B0[j].z + A0[j].w * B0[j].w
                        + A1[j].x * B1[j].x + A1[j].y * B1[j].y
                        + A1[j].z * B1[j].z + A1[j].w * B1[j].w;
                #pragma unroll
                for (int off = 8; off > 0; off >>= 1)
                    d += __shfl_xor_sync(hmask, d, off);
                float sx = d * g_inv_nrm[r[k]] * g_inv_nrm[c[k]];
                s[k] = (sx < SIM_THRESH) ? 0.0f : sx;
            }
        }
    }

    cudaTriggerProgrammaticLaunchCompletion();

    if (hl == 0) {
        #pragma unroll
        for (int k = 0; k < 4; k++) {
            if (!valid[k]) continue;
            long long e = e_base + 2 * k + half;
            g_sim[e] = s[k];
            if (s[k] != 0.0f) atomicAdd(&g_row_sum[r[k]], s[k]);  // s >= 0
        }
    }
}

// ---------------------------------------------------------------------------
// Kernel 3: finish — 4 consecutive edges per thread with vector loads
// (int4 ei + float4 ew + float4 sim), random gathers only for row_sum,
// __expf (rel err ~5e-7). PDL secondary.
// (inputs guarantee row != col, so the lam/diagonal term is always zero)
// ---------------------------------------------------------------------------
__global__ void finish_kernel(const int* __restrict__ ei,
                              const float* __restrict__ edge_weight,
                              const float* __restrict__ gate,
                              float* __restrict__ out,
                              int n_edge) {
    long long e_base = (long long)(blockIdx.x * blockDim.x + threadIdx.x) * 4;
    if (e_base >= n_edge) { cudaGridDependencySynchronize(); return; }

    bool full = (e_base + 4 <= (long long)n_edge);

    int4   ri;
    float4 wv;
    if (full) {
        ri = *reinterpret_cast<const int4*>(ei + e_base);
        wv = *reinterpret_cast<const float4*>(edge_weight + e_base);
    } else {
        int   rt[4]; float wt[4];
        #pragma unroll
        for (int k = 0; k < 4; k++) {
            bool ok = (e_base + k) < n_edge;
            rt[k] = ok ? ei[e_base + k] : 0;
            wt[k] = ok ? edge_weight[e_base + k] : 0.0f;
        }
        ri = make_int4(rt[0], rt[1], rt[2], rt[3]);
        wv = make_float4(wt[0], wt[1], wt[2], wt[3]);
    }
    float g = __ldg(gate);
    float one_m_g = 1.0f - g;

    // ---- wait for sim_kernel's writes (g_sim, g_row_sum)
    cudaGridDependencySynchronize();

    int   r[4] = {ri.x, ri.y, ri.z, ri.w};
    float rs[4];
    #pragma unroll
    for (int k = 0; k < 4; k++) rs[k] = g_row_sum[r[k]];

    float sm[4];
    if (full) {
        float4 sv = *reinterpret_cast<const float4*>(g_sim + e_base);
        sm[0] = sv.x; sm[1] = sv.y; sm[2] = sv.z; sm[3] = sv.w;
    } else {
        #pragma unroll
        for (int k = 0; k < 4; k++)
            sm[k] = ((e_base + k) < n_edge) ? g_sim[e_base + k] : 0.0f;
    }

    float w[4] = {wv.x, wv.y, wv.z, wv.w};
    float o[4];
    #pragma unroll
    for (int k = 0; k < 4; k++) {
        float denom = (rs[k] > 0.0f) ? rs[k] : 1.0f;
        float att = __expf(sm[k] / denom);
        o[k] = fmaxf(g * w[k] + one_m_g * att, 0.0f);
    }

    if (full) {
        *reinterpret_cast<float4*>(out + e_base) = make_float4(o[0], o[1], o[2], o[3]);
    } else {
        #pragma unroll
        for (int k = 0; k < 4; k++)
            if ((e_base + k) < n_edge) out[e_base + k] = o[k];
    }
}

// ---------------------------------------------------------------------------
extern "C" void kernel_launch(void* const* d_in, const int* in_sizes, int n_in,
                              void* d_out, int out_size) {
    const int*   ei   = (const int*)d_in[0];     // [2, E] int32
    const float* ew   = (const float*)d_in[1];   // [E]
    const float* feat = (const float*)d_in[2];   // [N, D]
    const float* gate = (const float*)d_in[3];   // [1]

    int n_edge = in_sizes[1];
    int n_node = in_sizes[2] / D_FEAT;

    // Kernel 1: 2 nodes per warp (also zeroes row_sum)
    {
        int n_warps = (n_node + 1) / 2;
        long long total = (long long)n_warps * 32;
        int blocks = (int)((total + 255) / 256);
        long long zero_blocks = ((long long)n_node + 255) / 256;
        if (zero_blocks > blocks) blocks = (int)zero_blocks;
        norm_kernel<<<blocks, 256>>>(feat, n_node);
    }

    cudaLaunchAttribute pdl_attr[1];
    pdl_attr[0].id = cudaLaunchAttributeProgrammaticStreamSerialization;
    pdl_attr[0].val.programmaticStreamSerializationAllowed = 1;

    // Kernel 2: 8 edges per warp (PDL secondary of norm)
    {
        int n_warps = (n_edge + 7) / 8;
        long long total = (long long)n_warps * 32;
        cudaLaunchConfig_t cfg = {};
        cfg.gridDim  = dim3((unsigned)((total + 255) / 256));
        cfg.blockDim = dim3(256);
        cfg.stream   = 0;
        cfg.attrs    = pdl_attr;
        cfg.numAttrs = 1;
        cudaLaunchKernelEx(&cfg, sim_kernel, ei, feat, n_edge);
    }
    // Kernel 3: 4 consecutive edges per thread, vectorized (PDL secondary)
    {
        int n_threads = (n_edge + 3) / 4;
        cudaLaunchConfig_t cfg = {};
        cfg.gridDim  = dim3((unsigned)((n_threads + 255) / 256));
        cfg.blockDim = dim3(256);
        cfg.stream   = 0;
        cfg.attrs    = pdl_attr;
        cfg.numAttrs = 1;
        cudaLaunchKernelEx(&cfg, finish_kernel, ei, ew, gate, (float*)d_out,
                           n_edge);
    }
}

// round 16
// speedup vs baseline: 1.0029x; 1.0029x over previous
#include <cuda_runtime.h>
#include <cuda_fp16.h>

// Problem constants (from reference): N=50000, D=128, E=625000
#define N_NODE   50000
#define D_FEAT   128
#define N_EDGE_MAX 625000
#define SIM_THRESH 0.1f
#define BAND 2.0e-3f   // rigorous fp16 dot error bound is ~1.1e-3; 2e-3 is safe

// Scratch (device globals — no allocation allowed in kernel_launch)
__device__ float g_inv_nrm[N_NODE];           // 1 / max(||f||, 1e-12)
__device__ float g_row_sum[N_NODE];           // L1 row sums of thresholded sim
__device__ __align__(16) float g_sim[N_EDGE_MAX];  // thresholded per-edge sim (exact fp32)
__device__ __align__(16) __half g_fn[(size_t)N_NODE * D_FEAT];  // normalized fp16 feats

// ---------------------------------------------------------------------------
// Kernel 1: per-node inverse norm — 4 nodes per warp (R12 best-total config),
// writes normalized fp16 features, zeroes row_sum. PDL trigger before the
// store phase.
// ---------------------------------------------------------------------------
__global__ void norm_kernel(const float* __restrict__ feat, int n_node) {
    int tid  = blockIdx.x * blockDim.x + threadIdx.x;
    int warp = tid >> 5;
    int lane = threadIdx.x & 31;

    if (tid < n_node) g_row_sum[tid] = 0.0f;

    int nb = warp * 4;
    if (nb >= n_node) return;

    const float4* F = reinterpret_cast<const float4*>(feat);
    float4 a[4];
    #pragma unroll
    for (int k = 0; k < 4; k++) {
        int n = nb + k;
        a[k] = (n < n_node) ? F[(size_t)n * 32 + lane] : make_float4(0, 0, 0, 0);
    }

    float s[4];
    #pragma unroll
    for (int k = 0; k < 4; k++)
        s[k] = a[k].x * a[k].x + a[k].y * a[k].y + a[k].z * a[k].z + a[k].w * a[k].w;
    #pragma unroll
    for (int off = 16; off > 0; off >>= 1) {
        #pragma unroll
        for (int k = 0; k < 4; k++)
            s[k] += __shfl_xor_sync(0xFFFFFFFFu, s[k], off);
    }

    cudaTriggerProgrammaticLaunchCompletion();

    #pragma unroll
    for (int k = 0; k < 4; k++) {
        int n = nb + k;
        if (n >= n_node) break;
        float inv = 1.0f / fmaxf(sqrtf(s[k]), 1e-12f);
        if (lane == 0) g_inv_nrm[n] = inv;
        __half2 h0 = __floats2half2_rn(a[k].x * inv, a[k].y * inv);
        __half2 h1 = __floats2half2_rn(a[k].z * inv, a[k].w * inv);
        uint2 p;
        p.x = *reinterpret_cast<unsigned*>(&h0);
        p.y = *reinterpret_cast<unsigned*>(&h1);
        reinterpret_cast<uint2*>(g_fn + (size_t)n * D_FEAT)[lane] = p;
    }
}

// ---------------------------------------------------------------------------
// Kernel 2: 8 edges per warp — 16 lanes per edge, LDG.128 fp16 gathers
// (8 front-batched loads = MLP 8), coalesced+shuffled index loads,
// pair-batched exact fp32 recompute for edges whose fp16 sim could pass the
// threshold (~14%). PDL trigger AFTER the recompute (measured best).
// Full-warp fast path: only the last warp does bounds checks.
// ---------------------------------------------------------------------------
__global__ void sim_kernel(const int* __restrict__ ei,
                           const float* __restrict__ feat,
                           int n_edge) {
    int warp = (blockIdx.x * blockDim.x + threadIdx.x) >> 5;
    int lane = threadIdx.x & 31;
    int half = lane >> 4;          // 0 or 1
    int hl   = lane & 15;          // lane within half-warp
    unsigned hmask = half ? 0xFFFF0000u : 0x0000FFFFu;

    long long e_base = (long long)warp * 8;
    if (e_base >= n_edge) { cudaGridDependencySynchronize(); return; }
    bool warp_full = (e_base + 8 <= (long long)n_edge);

    // ---- PDL prologue: edge indices are harness inputs, independent of norm
    int v = 0;
    {
        long long e = e_base + (lane & 7);
        if (lane < 16 && e < n_edge) {
            long long pos = (lane & 8) ? (long long)n_edge + e : e;
            v = ei[pos];
        }
    }
    int r[4], c[4];
    bool valid[4];
    #pragma unroll
    for (int k = 0; k < 4; k++) {
        int src = 2 * k + half;                       // this half-warp's edge
        r[k] = __shfl_sync(0xFFFFFFFFu, v, src);
        c[k] = __shfl_sync(0xFFFFFFFFu, v, 8 + src);
        valid[k] = warp_full || ((e_base + src) < n_edge);
    }

    // ---- wait for norm_kernel's writes (g_fn, g_inv_nrm, g_row_sum)
    cudaGridDependencySynchronize();

    // batched fp16 gathers: 8 independent LDG.128 (16 lanes x 16B = 256B/row)
    uint4 pa[4], pb[4];
    #pragma unroll
    for (int k = 0; k < 4; k++) {
        pa[k] = reinterpret_cast<const uint4*>(g_fn + (size_t)r[k] * D_FEAT)[hl];
        pb[k] = reinterpret_cast<const uint4*>(g_fn + (size_t)c[k] * D_FEAT)[hl];
    }

    float acc[4];
    #pragma unroll
    for (int k = 0; k < 4; k++) {
        const __half2* ha = reinterpret_cast<const __half2*>(&pa[k]);
        const __half2* hb = reinterpret_cast<const __half2*>(&pb[k]);
        float d = 0.0f;
        #pragma unroll
        for (int j = 0; j < 4; j++) {
            float2 x = __half22float2(ha[j]);
            float2 y = __half22float2(hb[j]);
            d += x.x * y.x + x.y * y.y;
        }
        acc[k] = d;
    }
    // interleaved 4-level half-warp reductions
    #pragma unroll
    for (int off = 8; off > 0; off >>= 1) {
        #pragma unroll
        for (int k = 0; k < 4; k++)
            acc[k] += __shfl_xor_sync(hmask, acc[k], off);
    }

    bool need[4];
    #pragma unroll
    for (int k = 0; k < 4; k++)
        need[k] = valid[k] && (acc[k] >= SIM_THRESH - BAND);  // half-warp uniform

    float s[4] = {0.0f, 0.0f, 0.0f, 0.0f};
    const float4* F = reinterpret_cast<const float4*>(feat);
    #pragma unroll
    for (int kk = 0; kk < 4; kk += 2) {
        float4 A0[2], A1[2], B0[2], B1[2];
        #pragma unroll
        for (int j = 0; j < 2; j++) {
            int k = kk + j;
            if (need[k]) {   // batch both edges' loads before either reduction
                const float4* FR = F + (size_t)r[k] * 32;
                const float4* FC = F + (size_t)c[k] * 32;
                A0[j] = FR[hl];      B0[j] = FC[hl];
                A1[j] = FR[hl + 16]; B1[j] = FC[hl + 16];
            }
        }
        #pragma unroll
        for (int j = 0; j < 2; j++) {
            int k = kk + j;
            if (need[k]) {
                float d = A0[j].x * B0[j].x + A0[j].y * B0[j].y
                        + A0[j].z * B0[j].z + A0[j].w * B0[j].w
                        + A1[j].x * B1[j].x + A1[j].y * B1[j].y
                        + A1[j].z * B1[j].z + A1[j].w * B1[j].w;
                #pragma unroll
                for (int off = 8; off > 0; off >>= 1)
                    d += __shfl_xor_sync(hmask, d, off);
                float sx = d * g_inv_nrm[r[k]] * g_inv_nrm[c[k]];
                s[k] = (sx < SIM_THRESH) ? 0.0f : sx;
            }
        }
    }

    cudaTriggerProgrammaticLaunchCompletion();

    if (hl == 0) {
        if (warp_full) {
            #pragma unroll
            for (int k = 0; k < 4; k++) {
                long long e = e_base + 2 * k + half;
                g_sim[e] = s[k];
                if (s[k] != 0.0f) atomicAdd(&g_row_sum[r[k]], s[k]);  // s >= 0
            }
        } else {
            #pragma unroll
            for (int k = 0; k < 4; k++) {
                if (!valid[k]) continue;
                long long e = e_base + 2 * k + half;
                g_sim[e] = s[k];
                if (s[k] != 0.0f) atomicAdd(&g_row_sum[r[k]], s[k]);
            }
        }
    }
}

// ---------------------------------------------------------------------------
// Kernel 3: finish — 4 consecutive edges per thread with vector loads
// (int4 ei + float4 ew + float4 sim), random gathers only for row_sum,
// __expf (rel err ~5e-7). PDL secondary.
// (inputs guarantee row != col, so the lam/diagonal term is always zero)
// ---------------------------------------------------------------------------
__global__ void finish_kernel(const int* __restrict__ ei,
                              const float* __restrict__ edge_weight,
                              const float* __restrict__ gate,
                              float* __restrict__ out,
                              int n_edge) {
    long long e_base = (long long)(blockIdx.x * blockDim.x + threadIdx.x) * 4;
    if (e_base >= n_edge) { cudaGridDependencySynchronize(); return; }

    bool full = (e_base + 4 <= (long long)n_edge);

    int4   ri;
    float4 wv;
    if (full) {
        ri = *reinterpret_cast<const int4*>(ei + e_base);
        wv = *reinterpret_cast<const float4*>(edge_weight + e_base);
    } else {
        int   rt[4]; float wt[4];
        #pragma unroll
        for (int k = 0; k < 4; k++) {
            bool ok = (e_base + k) < n_edge;
            rt[k] = ok ? ei[e_base + k] : 0;
            wt[k] = ok ? edge_weight[e_base + k] : 0.0f;
        }
        ri = make_int4(rt[0], rt[1], rt[2], rt[3]);
        wv = make_float4(wt[0], wt[1], wt[2], wt[3]);
    }
    float g = __ldg(gate);
    float one_m_g = 1.0f - g;

    // ---- wait for sim_kernel's writes (g_sim, g_row_sum)
    cudaGridDependencySynchronize();

    int   r[4] = {ri.x, ri.y, ri.z, ri.w};
    float rs[4];
    #pragma unroll
    for (int k = 0; k < 4; k++) rs[k] = g_row_sum[r[k]];

    float sm[4];
    if (full) {
        float4 sv = *reinterpret_cast<const float4*>(g_sim + e_base);
        sm[0] = sv.x; sm[1] = sv.y; sm[2] = sv.z; sm[3] = sv.w;
    } else {
        #pragma unroll
        for (int k = 0; k < 4; k++)
            sm[k] = ((e_base + k) < n_edge) ? g_sim[e_base + k] : 0.0f;
    }

    float w[4] = {wv.x, wv.y, wv.z, wv.w};
    float o[4];
    #pragma unroll
    for (int k = 0; k < 4; k++) {
        float denom = (rs[k] > 0.0f) ? rs[k] : 1.0f;
        float att = __expf(sm[k] / denom);
        o[k] = fmaxf(g * w[k] + one_m_g * att, 0.0f);
    }

    if (full) {
        *reinterpret_cast<float4*>(out + e_base) = make_float4(o[0], o[1], o[2], o[3]);
    } else {
        #pragma unroll
        for (int k = 0; k < 4; k++)
            if ((e_base + k) < n_edge) out[e_base + k] = o[k];
    }
}

// ---------------------------------------------------------------------------
extern "C" void kernel_launch(void* const* d_in, const int* in_sizes, int n_in,
                              void* d_out, int out_size) {
    const int*   ei   = (const int*)d_in[0];     // [2, E] int32
    const float* ew   = (const float*)d_in[1];   // [E]
    const float* feat = (const float*)d_in[2];   // [N, D]
    const float* gate = (const float*)d_in[3];   // [1]

    int n_edge = in_sizes[1];
    int n_node = in_sizes[2] / D_FEAT;

    // Kernel 1: 4 nodes per warp (also zeroes row_sum)
    {
        int n_warps = (n_node + 3) / 4;
        long long total = (long long)n_warps * 32;
        int blocks = (int)((total + 255) / 256);
        long long zero_blocks = ((long long)n_node + 255) / 256;
        if (zero_blocks > blocks) blocks = (int)zero_blocks;
        norm_kernel<<<blocks, 256>>>(feat, n_node);
    }

    cudaLaunchAttribute pdl_attr[1];
    pdl_attr[0].id = cudaLaunchAttributeProgrammaticStreamSerialization;
    pdl_attr[0].val.programmaticStreamSerializationAllowed = 1;

    // Kernel 2: 8 edges per warp (PDL secondary of norm)
    {
        int n_warps = (n_edge + 7) / 8;
        long long total = (long long)n_warps * 32;
        cudaLaunchConfig_t cfg = {};
        cfg.gridDim  = dim3((unsigned)((total + 255) / 256));
        cfg.blockDim = dim3(256);
        cfg.stream   = 0;
        cfg.attrs    = pdl_attr;
        cfg.numAttrs = 1;
        cudaLaunchKernelEx(&cfg, sim_kernel, ei, feat, n_edge);
    }
    // Kernel 3: 4 consecutive edges per thread, vectorized (PDL secondary)
    {
        int n_threads = (n_edge + 3) / 4;
        cudaLaunchConfig_t cfg = {};
        cfg.gridDim  = dim3((unsigned)((n_threads + 255) / 256));
        cfg.blockDim = dim3(256);
        cfg.stream   = 0;
        cfg.attrs    = pdl_attr;
        cfg.numAttrs = 1;
        cudaLaunchKernelEx(&cfg, finish_kernel, ei, ew, gate, (float*)d_out,
                           n_edge);
    }
}

// round 17
// speedup vs baseline: 1.0040x; 1.0011x over previous
#include <cuda_runtime.h>
#include <cuda_fp16.h>

// Problem constants (from reference): N=50000, D=128, E=625000
#define N_NODE   50000
#define D_FEAT   128
#define N_EDGE_MAX 625000
#define SIM_THRESH 0.1f
#define BAND 2.0e-3f   // rigorous fp16 dot error bound is ~1.1e-3; 2e-3 is safe

// Scratch (device globals — no allocation allowed in kernel_launch)
__device__ float g_inv_nrm[N_NODE];           // 1 / max(||f||, 1e-12)
__device__ float g_row_sum[N_NODE];           // L1 row sums of thresholded sim
__device__ __align__(16) float g_sim[N_EDGE_MAX];  // thresholded per-edge sim (exact fp32)
__device__ __align__(16) __half g_fn[(size_t)N_NODE * D_FEAT];  // normalized fp16 feats

// ---------------------------------------------------------------------------
// Kernel 1: per-node inverse norm — 4 nodes per warp (R12 best-total config),
// writes normalized fp16 features, zeroes row_sum. PDL trigger before the
// store phase.
// ---------------------------------------------------------------------------
__global__ void norm_kernel(const float* __restrict__ feat, int n_node) {
    int tid  = blockIdx.x * blockDim.x + threadIdx.x;
    int warp = tid >> 5;
    int lane = threadIdx.x & 31;

    if (tid < n_node) g_row_sum[tid] = 0.0f;

    int nb = warp * 4;
    if (nb >= n_node) return;

    const float4* F = reinterpret_cast<const float4*>(feat);
    float4 a[4];
    #pragma unroll
    for (int k = 0; k < 4; k++) {
        int n = nb + k;
        a[k] = (n < n_node) ? F[(size_t)n * 32 + lane] : make_float4(0, 0, 0, 0);
    }

    float s[4];
    #pragma unroll
    for (int k = 0; k < 4; k++)
        s[k] = a[k].x * a[k].x + a[k].y * a[k].y + a[k].z * a[k].z + a[k].w * a[k].w;
    #pragma unroll
    for (int off = 16; off > 0; off >>= 1) {
        #pragma unroll
        for (int k = 0; k < 4; k++)
            s[k] += __shfl_xor_sync(0xFFFFFFFFu, s[k], off);
    }

    cudaTriggerProgrammaticLaunchCompletion();

    #pragma unroll
    for (int k = 0; k < 4; k++) {
        int n = nb + k;
        if (n >= n_node) break;
        float inv = 1.0f / fmaxf(sqrtf(s[k]), 1e-12f);
        if (lane == 0) g_inv_nrm[n] = inv;
        __half2 h0 = __floats2half2_rn(a[k].x * inv, a[k].y * inv);
        __half2 h1 = __floats2half2_rn(a[k].z * inv, a[k].w * inv);
        uint2 p;
        p.x = *reinterpret_cast<unsigned*>(&h0);
        p.y = *reinterpret_cast<unsigned*>(&h1);
        reinterpret_cast<uint2*>(g_fn + (size_t)n * D_FEAT)[lane] = p;
    }
}

// ---------------------------------------------------------------------------
// Kernel 2: 8 edges per warp — 16 lanes per edge, LDG.128 fp16 gathers
// (8 front-batched loads = MLP 8), coalesced+shuffled index loads,
// pair-batched exact fp32 recompute for edges whose fp16 sim could pass the
// threshold (~14%). Random-row gathers use __ldcg (L2-only): per-SM row reuse
// probability is ~2%, so L1 allocation is pure tag-churn overhead.
// PDL trigger AFTER the recompute (measured best).
// ---------------------------------------------------------------------------
__global__ void sim_kernel(const int* __restrict__ ei,
                           const float* __restrict__ feat,
                           int n_edge) {
    int warp = (blockIdx.x * blockDim.x + threadIdx.x) >> 5;
    int lane = threadIdx.x & 31;
    int half = lane >> 4;          // 0 or 1
    int hl   = lane & 15;          // lane within half-warp
    unsigned hmask = half ? 0xFFFF0000u : 0x0000FFFFu;

    long long e_base = (long long)warp * 8;
    if (e_base >= n_edge) { cudaGridDependencySynchronize(); return; }

    // ---- PDL prologue: edge indices are harness inputs, independent of norm
    int v = 0;
    {
        long long e = e_base + (lane & 7);
        if (lane < 16 && e < n_edge) {
            long long pos = (lane & 8) ? (long long)n_edge + e : e;
            v = ei[pos];
        }
    }
    int r[4], c[4];
    bool valid[4];
    #pragma unroll
    for (int k = 0; k < 4; k++) {
        int src = 2 * k + half;                       // this half-warp's edge
        r[k] = __shfl_sync(0xFFFFFFFFu, v, src);
        c[k] = __shfl_sync(0xFFFFFFFFu, v, 8 + src);
        valid[k] = (e_base + src) < n_edge;
    }

    // ---- wait for norm_kernel's writes (g_fn, g_inv_nrm, g_row_sum)
    cudaGridDependencySynchronize();

    // batched fp16 gathers: 8 independent LDG.128 (16 lanes x 16B = 256B/row),
    // L2-only caching (no L1 reuse to exploit)
    uint4 pa[4], pb[4];
    #pragma unroll
    for (int k = 0; k < 4; k++) {
        pa[k] = __ldcg(reinterpret_cast<const uint4*>(g_fn + (size_t)r[k] * D_FEAT) + hl);
        pb[k] = __ldcg(reinterpret_cast<const uint4*>(g_fn + (size_t)c[k] * D_FEAT) + hl);
    }

    float acc[4];
    #pragma unroll
    for (int k = 0; k < 4; k++) {
        const __half2* ha = reinterpret_cast<const __half2*>(&pa[k]);
        const __half2* hb = reinterpret_cast<const __half2*>(&pb[k]);
        float d = 0.0f;
        #pragma unroll
        for (int j = 0; j < 4; j++) {
            float2 x = __half22float2(ha[j]);
            float2 y = __half22float2(hb[j]);
            d += x.x * y.x + x.y * y.y;
        }
        acc[k] = d;
    }
    // interleaved 4-level half-warp reductions
    #pragma unroll
    for (int off = 8; off > 0; off >>= 1) {
        #pragma unroll
        for (int k = 0; k < 4; k++)
            acc[k] += __shfl_xor_sync(hmask, acc[k], off);
    }

    bool need[4];
    #pragma unroll
    for (int k = 0; k < 4; k++)
        need[k] = valid[k] && (acc[k] >= SIM_THRESH - BAND);  // half-warp uniform

    float s[4] = {0.0f, 0.0f, 0.0f, 0.0f};
    const float4* F = reinterpret_cast<const float4*>(feat);
    #pragma unroll
    for (int kk = 0; kk < 4; kk += 2) {
        float4 A0[2], A1[2], B0[2], B1[2];
        #pragma unroll
        for (int j = 0; j < 2; j++) {
            int k = kk + j;
            if (need[k]) {   // batch both edges' loads before either reduction
                const float4* FR = F + (size_t)r[k] * 32;
                const float4* FC = F + (size_t)c[k] * 32;
                A0[j] = __ldcg(FR + hl);      B0[j] = __ldcg(FC + hl);
                A1[j] = __ldcg(FR + hl + 16); B1[j] = __ldcg(FC + hl + 16);
            }
        }
        #pragma unroll
        for (int j = 0; j < 2; j++) {
            int k = kk + j;
            if (need[k]) {
                float d = A0[j].x * B0[j].x + A0[j].y * B0[j].y
                        + A0[j].z * B0[j].z + A0[j].w * B0[j].w
                        + A1[j].x * B1[j].x + A1[j].y * B1[j].y
                        + A1[j].z * B1[j].z + A1[j].w * B1[j].w;
                #pragma unroll
                for (int off = 8; off > 0; off >>= 1)
                    d += __shfl_xor_sync(hmask, d, off);
                float sx = d * g_inv_nrm[r[k]] * g_inv_nrm[c[k]];
                s[k] = (sx < SIM_THRESH) ? 0.0f : sx;
            }
        }
    }

    cudaTriggerProgrammaticLaunchCompletion();

    if (hl == 0) {
        #pragma unroll
        for (int k = 0; k < 4; k++) {
            if (!valid[k]) continue;
            long long e = e_base + 2 * k + half;
            g_sim[e] = s[k];
            if (s[k] != 0.0f) atomicAdd(&g_row_sum[r[k]], s[k]);  // s >= 0
        }
    }
}

// ---------------------------------------------------------------------------
// Kernel 3: finish — 4 consecutive edges per thread with vector loads
// (int4 ei + float4 ew + float4 sim), random gathers only for row_sum
// (high-reuse 200KB array: default L1 caching kept), __expf. PDL secondary.
// (inputs guarantee row != col, so the lam/diagonal term is always zero)
// ---------------------------------------------------------------------------
__global__ void finish_kernel(const int* __restrict__ ei,
                              const float* __restrict__ edge_weight,
                              const float* __restrict__ gate,
                              float* __restrict__ out,
                              int n_edge) {
    long long e_base = (long long)(blockIdx.x * blockDim.x + threadIdx.x) * 4;
    if (e_base >= n_edge) { cudaGridDependencySynchronize(); return; }

    bool full = (e_base + 4 <= (long long)n_edge);

    int4   ri;
    float4 wv;
    if (full) {
        ri = *reinterpret_cast<const int4*>(ei + e_base);
        wv = *reinterpret_cast<const float4*>(edge_weight + e_base);
    } else {
        int   rt[4]; float wt[4];
        #pragma unroll
        for (int k = 0; k < 4; k++) {
            bool ok = (e_base + k) < n_edge;
            rt[k] = ok ? ei[e_base + k] : 0;
            wt[k] = ok ? edge_weight[e_base + k] : 0.0f;
        }
        ri = make_int4(rt[0], rt[1], rt[2], rt[3]);
        wv = make_float4(wt[0], wt[1], wt[2], wt[3]);
    }
    float g = __ldg(gate);
    float one_m_g = 1.0f - g;

    // ---- wait for sim_kernel's writes (g_sim, g_row_sum)
    cudaGridDependencySynchronize();

    int   r[4] = {ri.x, ri.y, ri.z, ri.w};
    float rs[4];
    #pragma unroll
    for (int k = 0; k < 4; k++) rs[k] = g_row_sum[r[k]];

    float sm[4];
    if (full) {
        float4 sv = *reinterpret_cast<const float4*>(g_sim + e_base);
        sm[0] = sv.x; sm[1] = sv.y; sm[2] = sv.z; sm[3] = sv.w;
    } else {
        #pragma unroll
        for (int k = 0; k < 4; k++)
            sm[k] = ((e_base + k) < n_edge) ? g_sim[e_base + k] : 0.0f;
    }

    float w[4] = {wv.x, wv.y, wv.z, wv.w};
    float o[4];
    #pragma unroll
    for (int k = 0; k < 4; k++) {
        float denom = (rs[k] > 0.0f) ? rs[k] : 1.0f;
        float att = __expf(sm[k] / denom);
        o[k] = fmaxf(g * w[k] + one_m_g * att, 0.0f);
    }

    if (full) {
        *reinterpret_cast<float4*>(out + e_base) = make_float4(o[0], o[1], o[2], o[3]);
    } else {
        #pragma unroll
        for (int k = 0; k < 4; k++)
            if ((e_base + k) < n_edge) out[e_base + k] = o[k];
    }
}

// ---------------------------------------------------------------------------
extern "C" void kernel_launch(void* const* d_in, const int* in_sizes, int n_in,
                              void* d_out, int out_size) {
    const int*   ei   = (const int*)d_in[0];     // [2, E] int32
    const float* ew   = (const float*)d_in[1];   // [E]
    const float* feat = (const float*)d_in[2];   // [N, D]
    const float* gate = (const float*)d_in[3];   // [1]

    int n_edge = in_sizes[1];
    int n_node = in_sizes[2] / D_FEAT;

    // Kernel 1: 4 nodes per warp (also zeroes row_sum)
    {
        int n_warps = (n_node + 3) / 4;
        long long total = (long long)n_warps * 32;
        int blocks = (int)((total + 255) / 256);
        long long zero_blocks = ((long long)n_node + 255) / 256;
        if (zero_blocks > blocks) blocks = (int)zero_blocks;
        norm_kernel<<<blocks, 256>>>(feat, n_node);
    }

    cudaLaunchAttribute pdl_attr[1];
    pdl_attr[0].id = cudaLaunchAttributeProgrammaticStreamSerialization;
    pdl_attr[0].val.programmaticStreamSerializationAllowed = 1;

    // Kernel 2: 8 edges per warp (PDL secondary of norm)
    {
        int n_warps = (n_edge + 7) / 8;
        long long total = (long long)n_warps * 32;
        cudaLaunchConfig_t cfg = {};
        cfg.gridDim  = dim3((unsigned)((total + 255) / 256));
        cfg.blockDim = dim3(256);
        cfg.stream   = 0;
        cfg.attrs    = pdl_attr;
        cfg.numAttrs = 1;
        cudaLaunchKernelEx(&cfg, sim_kernel, ei, feat, n_edge);
    }
    // Kernel 3: 4 consecutive edges per thread, vectorized (PDL secondary)
    {
        int n_threads = (n_edge + 3) / 4;
        cudaLaunchConfig_t cfg = {};
        cfg.gridDim  = dim3((unsigned)((n_threads + 255) / 256));
        cfg.blockDim = dim3(256);
        cfg.stream   = 0;
        cfg.attrs    = pdl_attr;
        cfg.numAttrs = 1;
        cudaLaunchKernelEx(&cfg, finish_kernel, ei, ew, gate, (float*)d_out,
                           n_edge);
    }
}